// round 1
// baseline (speedup 1.0000x reference)
#include <cuda_runtime.h>
#include <math.h>

// Problem constants
#define Bn 32
#define Hn 14
#define Wn 14
#define Cn 32
#define Kn 64
#define KSn 5
#define Pn 100      // 10x10 output positions
#define Mn 800      // ks*ks*C
#define Nn 196      // H*W

// Scratch (device globals -- no allocations allowed)
__device__ float g_mup[Bn*Pn*Mn];   // mu patches   [b][p][m]
__device__ float g_dgp[Bn*Pn*Mn];   // diag patches [b][p][m]
__device__ float g_G[Bn*Pn*Pn];     // Gram         [b][p][q]
__device__ float g_v1[Bn*Pn*Kn];    // dsg @ w^2    [b][p][k]
__device__ float g_tr[Bn*Pn];       // row sums of dsg
__device__ float g_sp[Kn];          // softplus(w_sigma)
__device__ float g_wsq[Mn*Kn];      // w^2 reshaped [m][k]

// ---------------------------------------------------------------------------
// Kernel 1: gather mu patches + Sigma diagonal patches, and square weights.
// idx over B*P*M = 2,560,000
// ---------------------------------------------------------------------------
__global__ __launch_bounds__(256) void k_gather(const float* __restrict__ mu_in,
                                                const float* __restrict__ Sigma_in,
                                                const float* __restrict__ w_mu) {
    int idx = blockIdx.x * 256 + threadIdx.x;
    if (idx < Mn * Kn) {
        float w = w_mu[idx];
        g_wsq[idx] = w * w;
    }
    if (idx >= Bn * Pn * Mn) return;
    int m  = idx % Mn;
    int bp = idx / Mn;
    int p  = bp % Pn;
    int b  = bp / Pn;
    int c  = m & 31;          // C = 32
    int ij = m >> 5;
    int j  = ij % KSn;
    int i  = ij / KSn;
    int y  = p / 10 + i;
    int x  = p % 10 + j;
    g_mup[idx] = mu_in[((b * Hn + y) * Wn + x) * Cn + c];
    int n = y * Wn + x;
    // Sigma_in[b][n][n][c]
    g_dgp[idx] = Sigma_in[(long long)b * (Nn * Nn * Cn) + (long long)n * (Nn * Cn + Cn) + c];
}

// ---------------------------------------------------------------------------
// Kernel 2: tr[b,p] = sum_m dgp ; sp[k] = softplus(w_sigma[k])
// ---------------------------------------------------------------------------
__global__ __launch_bounds__(256) void k_trsp(const float* __restrict__ w_sigma) {
    int idx = blockIdx.x * 256 + threadIdx.x;
    if (idx < Bn * Pn) {
        const float4* row = (const float4*)(g_dgp + (size_t)idx * Mn);
        float s = 0.f;
#pragma unroll 4
        for (int t = 0; t < Mn / 4; t++) {
            float4 v = row[t];
            s += v.x + v.y + v.z + v.w;
        }
        g_tr[idx] = s;
    } else if (idx < Bn * Pn + Kn) {
        int k = idx - Bn * Pn;
        g_sp[k] = log1pf(expf(w_sigma[k]));
    }
}

// ---------------------------------------------------------------------------
// Kernel 3: mu_out[b,p,k] = mup[b,p,:] . w[:,k]
//           v1[b,p,k]     = dgp[b,p,:] . wsq[:,k]
// grid (32, 7): 16 p-rows per block; block 128 = 8 row-pairs x 16 k-quads
// ---------------------------------------------------------------------------
__global__ __launch_bounds__(128) void k_muv1(const float* __restrict__ w_mu,
                                              float* __restrict__ mu_out,
                                              int write_mu) {
    int b   = blockIdx.x;
    int tid = threadIdx.x;
    int kq  = tid & 15;
    int k4  = kq * 4;
    int rp  = tid >> 4;                  // 0..7
    int p0  = blockIdx.y * 16 + rp * 2;
    int p1  = p0 + 1;
    int pc0 = p0 < Pn ? p0 : Pn - 1;
    int pc1 = p1 < Pn ? p1 : Pn - 1;
    const float* mr0 = g_mup + (size_t)(b * Pn + pc0) * Mn;
    const float* mr1 = g_mup + (size_t)(b * Pn + pc1) * Mn;
    const float* dr0 = g_dgp + (size_t)(b * Pn + pc0) * Mn;
    const float* dr1 = g_dgp + (size_t)(b * Pn + pc1) * Mn;

    float4 aM0 = {0,0,0,0}, aM1 = {0,0,0,0};
    float4 aV0 = {0,0,0,0}, aV1 = {0,0,0,0};

#pragma unroll 4
    for (int m = 0; m < Mn; m++) {
        float a0 = __ldg(mr0 + m);
        float a1 = __ldg(mr1 + m);
        float d0 = __ldg(dr0 + m);
        float d1 = __ldg(dr1 + m);
        float4 w4 = __ldg((const float4*)(w_mu  + m * Kn + k4));
        float4 s4 = __ldg((const float4*)(g_wsq + m * Kn + k4));
        aM0.x = fmaf(a0, w4.x, aM0.x); aM0.y = fmaf(a0, w4.y, aM0.y);
        aM0.z = fmaf(a0, w4.z, aM0.z); aM0.w = fmaf(a0, w4.w, aM0.w);
        aM1.x = fmaf(a1, w4.x, aM1.x); aM1.y = fmaf(a1, w4.y, aM1.y);
        aM1.z = fmaf(a1, w4.z, aM1.z); aM1.w = fmaf(a1, w4.w, aM1.w);
        aV0.x = fmaf(d0, s4.x, aV0.x); aV0.y = fmaf(d0, s4.y, aV0.y);
        aV0.z = fmaf(d0, s4.z, aV0.z); aV0.w = fmaf(d0, s4.w, aV0.w);
        aV1.x = fmaf(d1, s4.x, aV1.x); aV1.y = fmaf(d1, s4.y, aV1.y);
        aV1.z = fmaf(d1, s4.z, aV1.z); aV1.w = fmaf(d1, s4.w, aV1.w);
    }
    if (p0 < Pn) {
        if (write_mu) *(float4*)(mu_out + (size_t)(b * Pn + p0) * Kn + k4) = aM0;
        *(float4*)(g_v1 + (size_t)(b * Pn + p0) * Kn + k4) = aV0;
    }
    if (p1 < Pn) {
        if (write_mu) *(float4*)(mu_out + (size_t)(b * Pn + p1) * Kn + k4) = aM1;
        *(float4*)(g_v1 + (size_t)(b * Pn + p1) * Kn + k4) = aV1;
    }
}

// ---------------------------------------------------------------------------
// Kernel 4: G[b,p,q] = mup[b,p,:] . mup[b,q,:]
// grid (32, 2, 2): 50x50 tile per block; block (13,13), 4x4 per thread
// (interleaved, covers 52x52, out-of-tile results discarded)
// ---------------------------------------------------------------------------
#define GCH 16
__global__ void k_gram() {
    __shared__ float As[GCH][56];
    __shared__ float Bs[GCH][56];
    int b  = blockIdx.x;
    int pt = blockIdx.y;
    int qt = blockIdx.z;
    int tx = threadIdx.x;   // 0..12
    int ty = threadIdx.y;   // 0..12
    int lid = ty * 13 + tx; // 0..168

    float acc[4][4];
#pragma unroll
    for (int i = 0; i < 4; i++)
#pragma unroll
        for (int j = 0; j < 4; j++) acc[i][j] = 0.f;

    for (int mc = 0; mc < Mn; mc += GCH) {
        // stage: 2 halves * 52 rows * 4 float4-segments = 416 items
        for (int t = lid; t < 416; t += 169) {
            int half = t / 208;
            int tt   = t % 208;
            int row  = tt / 4;            // 0..51
            int mseg = (tt % 4) * 4;      // 0,4,8,12
            int tile = half ? qt : pt;
            int pg   = tile * 50 + row;
            if (pg > Pn - 1) pg = Pn - 1; // clamped rows only feed discarded outputs
            float4 v = *(const float4*)(g_mup + (size_t)(b * Pn + pg) * Mn + mc + mseg);
            float* dst = half ? &Bs[0][0] : &As[0][0];
            dst[(mseg + 0) * 56 + row] = v.x;
            dst[(mseg + 1) * 56 + row] = v.y;
            dst[(mseg + 2) * 56 + row] = v.z;
            dst[(mseg + 3) * 56 + row] = v.w;
        }
        __syncthreads();
#pragma unroll
        for (int ml = 0; ml < GCH; ml++) {
            float a[4], bb[4];
#pragma unroll
            for (int i = 0; i < 4; i++) a[i]  = As[ml][ty + 13 * i];
#pragma unroll
            for (int j = 0; j < 4; j++) bb[j] = Bs[ml][tx + 13 * j];
#pragma unroll
            for (int i = 0; i < 4; i++)
#pragma unroll
                for (int j = 0; j < 4; j++) acc[i][j] = fmaf(a[i], bb[j], acc[i][j]);
        }
        __syncthreads();
    }

#pragma unroll
    for (int i = 0; i < 4; i++) {
        int pl = ty + 13 * i;
        if (pl >= 50) continue;
        int p = pt * 50 + pl;
#pragma unroll
        for (int j = 0; j < 4; j++) {
            int ql = tx + 13 * j;
            if (ql >= 50) continue;
            int q = qt * 50 + ql;
            g_G[(size_t)b * (Pn * Pn) + p * Pn + q] = acc[i][j];
        }
    }
}

// ---------------------------------------------------------------------------
// Kernel 5: materialize Sigma_out [32,100,100,64] (float4 stores)
//   v = sp[k]*G[b,p,q] ; + (v1 + sp*tr) on p==q ; nan/inf -> 0 ; abs on q==k
// grid 20000 x 256, one float4 (4 k's) per thread
// ---------------------------------------------------------------------------
__global__ __launch_bounds__(256) void k_sigma(float* __restrict__ sigma_out) {
    int u = blockIdx.x * 256 + threadIdx.x;     // < 5,120,000
    int kq = u & 15;
    int k4 = kq * 4;
    int bpq = u >> 4;                           // b*10000 + p*100 + q
    int q  = bpq % Pn;
    int bp = bpq / Pn;
    int p  = bp % Pn;

    float g = __ldg(g_G + bpq);
    float4 s = *(const float4*)(g_sp + k4);
    float4 v;
    v.x = s.x * g; v.y = s.y * g; v.z = s.z * g; v.w = s.w * g;

    if (p == q) {
        float4 d = *(const float4*)(g_v1 + (size_t)bp * Kn + k4);
        float t = __ldg(g_tr + bp);
        v.x += d.x + s.x * t;
        v.y += d.y + s.y * t;
        v.z += d.z + s.z * t;
        v.w += d.w + s.w * t;
    }
    v.x = isfinite(v.x) ? v.x : 0.f;
    v.y = isfinite(v.y) ? v.y : 0.f;
    v.z = isfinite(v.z) ? v.z : 0.f;
    v.w = isfinite(v.w) ? v.w : 0.f;

    int dq = q - k4;   // abs on q == k (k < 64 always since q==k implies q<64.. covered)
    if (dq == 0)      v.x = fabsf(v.x);
    else if (dq == 1) v.y = fabsf(v.y);
    else if (dq == 2) v.z = fabsf(v.z);
    else if (dq == 3) v.w = fabsf(v.w);

    *(float4*)(sigma_out + (size_t)bpq * Kn + k4) = v;
}

// ---------------------------------------------------------------------------
extern "C" void kernel_launch(void* const* d_in, const int* in_sizes, int n_in,
                              void* d_out, int out_size) {
    const float* mu_in    = (const float*)d_in[0];
    const float* Sigma_in = (const float*)d_in[1];
    const float* w_mu     = (const float*)d_in[2];
    const float* w_sigma  = (const float*)d_in[3];
    float* out = (float*)d_out;

    // Output = [mu_out (32*10*10*64) | Sigma_out (32*100*100*64)], derived defensively.
    const long long sigma_elems = (long long)Bn * Pn * Pn * Kn;   // 20,480,000
    long long sigma_off = (long long)out_size - sigma_elems;
    if (sigma_off < 0) sigma_off = 0;
    int write_mu = (sigma_off >= (long long)Bn * Pn * Kn) ? 1 : 0;
    float* mu_out    = out;                  // offset 0
    float* sigma_out = out + sigma_off;

    k_gather<<<(Bn * Pn * Mn + 255) / 256, 256>>>(mu_in, Sigma_in, w_mu);
    k_trsp<<<(Bn * Pn + Kn + 255) / 256, 256>>>(w_sigma);
    k_muv1<<<dim3(Bn, 7), 128>>>(w_mu, mu_out, write_mu);
    k_gram<<<dim3(Bn, 2, 2), dim3(13, 13)>>>();
    k_sigma<<<(Bn * Pn * Pn * (Kn / 4) + 255) / 256, 256>>>(sigma_out);
}

// round 2
// speedup vs baseline: 3.0212x; 3.0212x over previous
#include <cuda_runtime.h>
#include <math.h>

#define Bn 32
#define Hn 14
#define Wn 14
#define Cn 32
#define Kn 64
#define KSn 5
#define Pn 100      // 10x10 output positions
#define Mn 800      // ks*ks*C
#define Nn 196      // H*W

typedef unsigned long long ull;

// Scratch (device globals -- no allocations allowed)
__device__ float g_mup[Bn*Pn*Mn];   // mu patches   [b][p][m]
__device__ float g_dgp[Bn*Pn*Mn];   // diag patches [b][p][m]
__device__ float g_G[Bn*Pn*Pn];     // Gram         [b][p][q]
__device__ float g_v1[Bn*Pn*Kn];    // diag_vals = dgp @ (w^2 + sp)
__device__ float g_sp[Kn];          // softplus(w_sigma)
__device__ float g_wsq2[Mn*Kn];     // w^2 + sp broadcast, [m][k]

__device__ __forceinline__ ull pack2(float x, float y) {
    ull r; asm("mov.b64 %0, {%1, %2};" : "=l"(r) : "f"(x), "f"(y)); return r;
}
__device__ __forceinline__ void unpack2(ull v, float &x, float &y) {
    asm("mov.b64 {%0, %1}, %2;" : "=f"(x), "=f"(y) : "l"(v));
}
__device__ __forceinline__ void fma2(ull &d, ull a, ull b) {
    asm("fma.rn.f32x2 %0, %1, %2, %0;" : "+l"(d) : "l"(a), "l"(b));
}

// ---------------------------------------------------------------------------
// Kernel 1: gather mu patches + Sigma diagonal patches; wsq2 = w^2 + sp; sp.
// ---------------------------------------------------------------------------
__global__ __launch_bounds__(256) void k_gather(const float* __restrict__ mu_in,
                                                const float* __restrict__ Sigma_in,
                                                const float* __restrict__ w_mu,
                                                const float* __restrict__ w_sigma) {
    int idx = blockIdx.x * 256 + threadIdx.x;
    if (idx < Mn * Kn) {
        int k = idx & 63;
        float w  = w_mu[idx];
        float sp = log1pf(expf(w_sigma[k]));
        g_wsq2[idx] = w * w + sp;
        if (idx < Kn) g_sp[idx] = sp;
    }
    if (idx >= Bn * Pn * Mn) return;
    int m  = idx % Mn;
    int bp = idx / Mn;
    int p  = bp % Pn;
    int b  = bp / Pn;
    int c  = m & 31;          // C = 32
    int ij = m >> 5;
    int j  = ij % KSn;
    int i  = ij / KSn;
    int y  = p / 10 + i;
    int x  = p % 10 + j;
    g_mup[idx] = mu_in[((b * Hn + y) * Wn + x) * Cn + c];
    int n = y * Wn + x;
    g_dgp[idx] = Sigma_in[(long long)b * (Nn * Nn * Cn) + (long long)n * (Nn * Cn + Cn) + c];
}

// ---------------------------------------------------------------------------
// Kernel 2: G[b,p,q] = mup[b,p,:] . mup[b,q,:]
// grid (32, 3): 3 symmetric 64x64 tiles; sel1 mirror-stored.
// block 256 = 16x16 threads, 4p x 4q micro-tile, f32x2 packed FMA.
// ---------------------------------------------------------------------------
#define GMC 32
__global__ __launch_bounds__(256) void k_gram() {
    __shared__ __align__(16) float AsmD[GMC][130];  // duplicated a: [m][2p]
    __shared__ __align__(16) float Bsm[GMC][68];    // [m][q]
    int b   = blockIdx.x;
    int sel = blockIdx.y;
    int pt = (sel == 2) ? 1 : 0;
    int qt = (sel == 0) ? 0 : 1;
    int t  = threadIdx.x;
    int tx = t & 15, ty = t >> 4;
    const float* Abase = g_mup + (size_t)b * (Pn * Mn);

    ull acc[4][2] = {};

    for (int mc = 0; mc < Mn; mc += GMC) {
#pragma unroll
        for (int r = 0; r < 2; r++) {           // stage A (dup)
            int f   = t + r * 256;
            int p_l = f >> 3;                   // 0..63
            int m_l = (f & 7) * 4;
            int prow = pt * 64 + p_l; if (prow > Pn - 1) prow = Pn - 1;
            float4 v = *(const float4*)(Abase + (size_t)prow * Mn + mc + m_l);
            *(ull*)&AsmD[m_l + 0][2 * p_l] = pack2(v.x, v.x);
            *(ull*)&AsmD[m_l + 1][2 * p_l] = pack2(v.y, v.y);
            *(ull*)&AsmD[m_l + 2][2 * p_l] = pack2(v.z, v.z);
            *(ull*)&AsmD[m_l + 3][2 * p_l] = pack2(v.w, v.w);
        }
#pragma unroll
        for (int r = 0; r < 2; r++) {           // stage B (transposed)
            int f   = t + r * 256;
            int q_l = f >> 3;
            int m_l = (f & 7) * 4;
            int qrow = qt * 64 + q_l; if (qrow > Pn - 1) qrow = Pn - 1;
            float4 v = *(const float4*)(Abase + (size_t)qrow * Mn + mc + m_l);
            Bsm[m_l + 0][q_l] = v.x;
            Bsm[m_l + 1][q_l] = v.y;
            Bsm[m_l + 2][q_l] = v.z;
            Bsm[m_l + 3][q_l] = v.w;
        }
        __syncthreads();
#pragma unroll
        for (int ml = 0; ml < GMC; ml++) {
            ulonglong2 bq = *(ulonglong2*)&Bsm[ml][4 * tx];
#pragma unroll
            for (int i = 0; i < 4; i++) {
                ull ad = *(ull*)&AsmD[ml][2 * (4 * ty + i)];
                fma2(acc[i][0], ad, bq.x);
                fma2(acc[i][1], ad, bq.y);
            }
        }
        __syncthreads();
    }

    float* Gb = g_G + (size_t)b * (Pn * Pn);
#pragma unroll
    for (int i = 0; i < 4; i++) {
        int p = pt * 64 + 4 * ty + i;
        float vv[4];
        unpack2(acc[i][0], vv[0], vv[1]);
        unpack2(acc[i][1], vv[2], vv[3]);
        if (p >= Pn) continue;
#pragma unroll
        for (int j = 0; j < 4; j++) {
            int q = qt * 64 + 4 * tx + j;
            if (q >= Pn) continue;
            Gb[p * Pn + q] = vv[j];
            if (sel == 1) Gb[q * Pn + p] = vv[j];   // mirror tile (1,0)
        }
    }
}

// ---------------------------------------------------------------------------
// Kernel 3: two GEMMs [100 x 64] = [100 x 800] x [800 x 64] per batch.
// z=0: mu_out = mup @ w_mu ; z=1: diag_vals = dgp @ wsq2
// grid (32, 4, 2); block 256 = 16 kq x 16 pg; 2p x 4k per thread, f32x2.
// ---------------------------------------------------------------------------
#define VMC 32
__global__ __launch_bounds__(256) void k_muv1(const float* __restrict__ w_mu,
                                              float* __restrict__ mu_out,
                                              int write_mu) {
    __shared__ __align__(16) float AsmD[VMC][66];   // duplicated a: [m][2p]
    __shared__ __align__(16) float Wsm[VMC][64];    // [m][k]
    int b     = blockIdx.x;
    int pbase = blockIdx.y * 32;
    int z     = blockIdx.z;
    const float* A = (z == 0 ? g_mup : g_dgp) + (size_t)b * (Pn * Mn);
    const float* W = (z == 0) ? w_mu : g_wsq2;
    int t  = threadIdx.x;
    int kq = t & 15, pg = t >> 4;
    int k4 = kq * 4;

    ull acc[2][2] = {};

    for (int mc = 0; mc < Mn; mc += VMC) {
        {                                       // stage A (dup): 32p x 32m
            int p_l = t >> 3;                   // 0..31
            int m_l = (t & 7) * 4;
            int prow = pbase + p_l; if (prow > Pn - 1) prow = Pn - 1;
            float4 v = *(const float4*)(A + (size_t)prow * Mn + mc + m_l);
            *(ull*)&AsmD[m_l + 0][2 * p_l] = pack2(v.x, v.x);
            *(ull*)&AsmD[m_l + 1][2 * p_l] = pack2(v.y, v.y);
            *(ull*)&AsmD[m_l + 2][2 * p_l] = pack2(v.z, v.z);
            *(ull*)&AsmD[m_l + 3][2 * p_l] = pack2(v.w, v.w);
        }
#pragma unroll
        for (int r = 0; r < 2; r++) {           // stage W: 32m x 64k
            int f  = t + r * 256;
            int m  = f >> 4;
            int kp = (f & 15) * 4;
            *(float4*)&Wsm[m][kp] = *(const float4*)(W + (size_t)(mc + m) * Kn + kp);
        }
        __syncthreads();
#pragma unroll
        for (int ml = 0; ml < VMC; ml++) {
            ulonglong2 wv = *(ulonglong2*)&Wsm[ml][k4];
            ull a0 = *(ull*)&AsmD[ml][2 * pg];
            ull a1 = *(ull*)&AsmD[ml][2 * (pg + 16)];
            fma2(acc[0][0], a0, wv.x); fma2(acc[0][1], a0, wv.y);
            fma2(acc[1][0], a1, wv.x); fma2(acc[1][1], a1, wv.y);
        }
        __syncthreads();
    }

    if (z == 0 && !write_mu) return;
    float* out = (z == 0) ? mu_out : g_v1;
#pragma unroll
    for (int s = 0; s < 2; s++) {
        int p = pbase + pg + 16 * s;
        if (p >= Pn) continue;
        float4 v;
        unpack2(acc[s][0], v.x, v.y);
        unpack2(acc[s][1], v.z, v.w);
        *(float4*)(out + (size_t)(b * Pn + p) * Kn + k4) = v;
    }
}

// ---------------------------------------------------------------------------
// Kernel 4: materialize Sigma_out [32,100,100,64] (float4 stores)
//   v = sp[k]*G[b,p,q] ; + diag_vals on p==q ; nan/inf -> 0 ; abs on q==k
// ---------------------------------------------------------------------------
__global__ __launch_bounds__(256) void k_sigma(float* __restrict__ sigma_out) {
    int u = blockIdx.x * 256 + threadIdx.x;     // < 5,120,000
    int kq = u & 15;
    int k4 = kq * 4;
    int bpq = u >> 4;                           // b*10000 + p*100 + q
    int q  = bpq % Pn;
    int bp = bpq / Pn;
    int p  = bp % Pn;

    float g = __ldg(g_G + bpq);
    float4 s = *(const float4*)(g_sp + k4);
    float4 v;
    v.x = s.x * g; v.y = s.y * g; v.z = s.z * g; v.w = s.w * g;

    if (p == q) {
        float4 d = *(const float4*)(g_v1 + (size_t)bp * Kn + k4);
        v.x += d.x; v.y += d.y; v.z += d.z; v.w += d.w;
    }
    v.x = isfinite(v.x) ? v.x : 0.f;
    v.y = isfinite(v.y) ? v.y : 0.f;
    v.z = isfinite(v.z) ? v.z : 0.f;
    v.w = isfinite(v.w) ? v.w : 0.f;

    int dq = q - k4;
    if (dq == 0)      v.x = fabsf(v.x);
    else if (dq == 1) v.y = fabsf(v.y);
    else if (dq == 2) v.z = fabsf(v.z);
    else if (dq == 3) v.w = fabsf(v.w);

    *(float4*)(sigma_out + (size_t)bpq * Kn + k4) = v;
}

// ---------------------------------------------------------------------------
extern "C" void kernel_launch(void* const* d_in, const int* in_sizes, int n_in,
                              void* d_out, int out_size) {
    const float* mu_in    = (const float*)d_in[0];
    const float* Sigma_in = (const float*)d_in[1];
    const float* w_mu     = (const float*)d_in[2];
    const float* w_sigma  = (const float*)d_in[3];
    float* out = (float*)d_out;

    const long long sigma_elems = (long long)Bn * Pn * Pn * Kn;   // 20,480,000
    long long sigma_off = (long long)out_size - sigma_elems;
    if (sigma_off < 0) sigma_off = 0;
    int write_mu = (sigma_off >= (long long)Bn * Pn * Kn) ? 1 : 0;
    float* mu_out    = out;
    float* sigma_out = out + sigma_off;

    k_gather<<<(Bn * Pn * Mn + 255) / 256, 256>>>(mu_in, Sigma_in, w_mu, w_sigma);
    k_gram<<<dim3(Bn, 3), 256>>>();
    k_muv1<<<dim3(Bn, 4, 2), 256>>>(w_mu, mu_out, write_mu);
    k_sigma<<<(Bn * Pn * Pn * (Kn / 4) + 255) / 256, 256>>>(sigma_out);
}

// round 4
// speedup vs baseline: 3.1443x; 1.0408x over previous
#include <cuda_runtime.h>
#include <math.h>

#define Bn 32
#define Hn 14
#define Wn 14
#define Cn 32
#define Kn 64
#define KSn 5
#define Pn 100      // 10x10 output positions
#define Mn 800      // ks*ks*C
#define Nn 196      // H*W
#define MS 5        // m-splits (800/5 = 160 = 10 chunks of 16)
#define MCH 16      // m chunk

typedef unsigned long long ull;

// Scratch (device globals -- no allocations allowed)
__device__ float g_mup[Bn*Pn*Mn];        // mu patches   [b][p][m]
__device__ float g_dgp[Bn*Pn*Mn];        // diag patches [b][p][m]
__device__ float g_Gp[MS*Bn*Pn*Pn];      // Gram partials [ms][b][p][q]
__device__ float g_muP[MS*Bn*Pn*Kn];     // mu_out partials
__device__ float g_v1P[MS*Bn*Pn*Kn];     // diag_vals partials
__device__ float g_v1[Bn*Pn*Kn];         // summed diag_vals
__device__ float g_sp[Kn];               // softplus(w_sigma)
__device__ float g_wsq2[Mn*Kn];          // w^2 + sp, [m][k]

__device__ __forceinline__ ull pack2(float x, float y) {
    ull r; asm("mov.b64 %0, {%1, %2};" : "=l"(r) : "f"(x), "f"(y)); return r;
}
__device__ __forceinline__ ull dup2(float x) {
    ull r; asm("mov.b64 %0, {%1, %1};" : "=l"(r) : "f"(x)); return r;
}
__device__ __forceinline__ void unpack2(ull v, float &x, float &y) {
    asm("mov.b64 {%0, %1}, %2;" : "=f"(x), "=f"(y) : "l"(v));
}
__device__ __forceinline__ void fma2(ull &d, ull a, ull b) {
    asm("fma.rn.f32x2 %0, %1, %2, %0;" : "+l"(d) : "l"(a), "l"(b));
}

// ---------------------------------------------------------------------------
// Kernel 1: gather mu patches + Sigma diagonal patches; wsq2 = w^2 + sp; sp.
// ---------------------------------------------------------------------------
__global__ __launch_bounds__(256) void k_gather(const float* __restrict__ mu_in,
                                                const float* __restrict__ Sigma_in,
                                                const float* __restrict__ w_mu,
                                                const float* __restrict__ w_sigma) {
    int idx = blockIdx.x * 256 + threadIdx.x;
    if (idx < Mn * Kn) {
        int k = idx & 63;
        float w  = w_mu[idx];
        float sp = log1pf(expf(w_sigma[k]));
        g_wsq2[idx] = w * w + sp;
        if (idx < Kn) g_sp[idx] = sp;
    }
    if (idx >= Bn * Pn * Mn) return;
    int m  = idx % Mn;
    int bp = idx / Mn;
    int p  = bp % Pn;
    int b  = bp / Pn;
    int c  = m & 31;
    int ij = m >> 5;
    int j  = ij % KSn;
    int i  = ij / KSn;
    int y  = p / 10 + i;
    int x  = p % 10 + j;
    g_mup[idx] = mu_in[((b * Hn + y) * Wn + x) * Cn + c];
    int n = y * Wn + x;
    g_dgp[idx] = Sigma_in[(long long)b * (Nn * Nn * Cn) + (long long)n * (Nn * Cn + Cn) + c];
}

// ---------------------------------------------------------------------------
// Kernel 2: Gram partials. grid (32, 3 sym-tiles, 5 m-splits), 128 threads.
// Tile 64x64, micro 8p x 4q per thread. Plain smem, dup-A via mov.b64.
// ---------------------------------------------------------------------------
__global__ __launch_bounds__(128) void k_gram() {
    __shared__ __align__(16) float As[MCH][68];
    __shared__ __align__(16) float Bs[MCH][68];
    int b   = blockIdx.x;
    int sel = blockIdx.y;
    int ms  = blockIdx.z;
    int pt = (sel == 2) ? 1 : 0;
    int qt = (sel == 0) ? 0 : 1;
    int t  = threadIdx.x;
    int qg = t & 15;       // 0..15 -> q strip of 4
    int pg = t >> 4;       // 0..7  -> p strip of 8
    const float* Abase = g_mup + (size_t)b * (Pn * Mn);

    // staging indices: 64 p-rows x (2 halves of 8 m) per matrix
    int sp_l = t & 63;
    int smh  = (t >> 6) * 8;
    int prow = pt * 64 + sp_l; if (prow > Pn - 1) prow = Pn - 1;
    int qrow = qt * 64 + sp_l; if (qrow > Pn - 1) qrow = Pn - 1;
    const float* Arow = Abase + (size_t)prow * Mn + ms * 160 + smh;
    const float* Brow = Abase + (size_t)qrow * Mn + ms * 160 + smh;

    ull acc[8][2] = {};

    for (int mc = 0; mc < 160; mc += MCH) {
        float4 a0 = *(const float4*)(Arow + mc);
        float4 a1 = *(const float4*)(Arow + mc + 4);
        float4 b0 = *(const float4*)(Brow + mc);
        float4 b1 = *(const float4*)(Brow + mc + 4);
        As[smh + 0][sp_l] = a0.x; As[smh + 1][sp_l] = a0.y;
        As[smh + 2][sp_l] = a0.z; As[smh + 3][sp_l] = a0.w;
        As[smh + 4][sp_l] = a1.x; As[smh + 5][sp_l] = a1.y;
        As[smh + 6][sp_l] = a1.z; As[smh + 7][sp_l] = a1.w;
        Bs[smh + 0][sp_l] = b0.x; Bs[smh + 1][sp_l] = b0.y;
        Bs[smh + 2][sp_l] = b0.z; Bs[smh + 3][sp_l] = b0.w;
        Bs[smh + 4][sp_l] = b1.x; Bs[smh + 5][sp_l] = b1.y;
        Bs[smh + 6][sp_l] = b1.z; Bs[smh + 7][sp_l] = b1.w;
        __syncthreads();
#pragma unroll
        for (int ml = 0; ml < MCH; ml++) {
            ulonglong2 bb = *(ulonglong2*)&Bs[ml][qg * 4];
            float4 av0 = *(float4*)&As[ml][pg * 8];
            float4 av1 = *(float4*)&As[ml][pg * 8 + 4];
            ull d;
            d = dup2(av0.x); fma2(acc[0][0], d, bb.x); fma2(acc[0][1], d, bb.y);
            d = dup2(av0.y); fma2(acc[1][0], d, bb.x); fma2(acc[1][1], d, bb.y);
            d = dup2(av0.z); fma2(acc[2][0], d, bb.x); fma2(acc[2][1], d, bb.y);
            d = dup2(av0.w); fma2(acc[3][0], d, bb.x); fma2(acc[3][1], d, bb.y);
            d = dup2(av1.x); fma2(acc[4][0], d, bb.x); fma2(acc[4][1], d, bb.y);
            d = dup2(av1.y); fma2(acc[5][0], d, bb.x); fma2(acc[5][1], d, bb.y);
            d = dup2(av1.z); fma2(acc[6][0], d, bb.x); fma2(acc[6][1], d, bb.y);
            d = dup2(av1.w); fma2(acc[7][0], d, bb.x); fma2(acc[7][1], d, bb.y);
        }
        __syncthreads();
    }

    float* Gp = g_Gp + ((size_t)ms * Bn + b) * (Pn * Pn);
#pragma unroll
    for (int i = 0; i < 8; i++) {
        int p = pt * 64 + pg * 8 + i;
        if (p >= Pn) continue;
        float vv[4];
        unpack2(acc[i][0], vv[0], vv[1]);
        unpack2(acc[i][1], vv[2], vv[3]);
#pragma unroll
        for (int j = 0; j < 4; j++) {
            int q = qt * 64 + qg * 4 + j;
            if (q >= Pn) continue;
            Gp[p * Pn + q] = vv[j];
            if (sel == 1) Gp[q * Pn + p] = vv[j];
        }
    }
}

// ---------------------------------------------------------------------------
// Kernel 3: muv1 partials. grid (32, 2 z, 5 m-splits), 128 threads.
// Tile 128p(pad) x 64k, micro 8p x 8k per thread.
// ---------------------------------------------------------------------------
__global__ __launch_bounds__(128) void k_muv1(const float* __restrict__ w_mu) {
    __shared__ __align__(16) float As[MCH][132];
    __shared__ __align__(16) float Ws[MCH][68];
    int b  = blockIdx.x;
    int z  = blockIdx.y;
    int ms = blockIdx.z;
    const float* A = (z == 0 ? g_mup : g_dgp) + (size_t)b * (Pn * Mn);
    const float* W = (z == 0) ? w_mu : g_wsq2;
    int t  = threadIdx.x;
    int kg = t & 7;        // 0..7  -> k strip of 8
    int pg = t >> 3;       // 0..15 -> p strip of 8

    int prow = t; if (prow > Pn - 1) prow = Pn - 1;   // 128 p rows, one per thread
    const float* Arow = A + (size_t)prow * Mn + ms * 160;

    ull acc[8][4] = {};

    for (int mc = 0; mc < 160; mc += MCH) {
        // stage A: 16m x 128p (thread loads 16 m for its p-row)
#pragma unroll
        for (int r = 0; r < 4; r++) {
            float4 v = *(const float4*)(Arow + mc + r * 4);
            As[r * 4 + 0][t] = v.x; As[r * 4 + 1][t] = v.y;
            As[r * 4 + 2][t] = v.z; As[r * 4 + 3][t] = v.w;
        }
        // stage W: 16m x 64k, coalesced
#pragma unroll
        for (int r = 0; r < 2; r++) {
            int f  = t + r * 128;
            int m  = f >> 4;
            int kp = (f & 15) * 4;
            *(float4*)&Ws[m][kp] = *(const float4*)(W + (size_t)(ms * 160 + mc + m) * Kn + kp);
        }
        __syncthreads();
#pragma unroll
        for (int ml = 0; ml < MCH; ml++) {
            ulonglong2 w0 = *(ulonglong2*)&Ws[ml][kg * 8];
            ulonglong2 w1 = *(ulonglong2*)&Ws[ml][kg * 8 + 4];
            float4 av0 = *(float4*)&As[ml][pg * 8];
            float4 av1 = *(float4*)&As[ml][pg * 8 + 4];
            ull d;
            d = dup2(av0.x); fma2(acc[0][0], d, w0.x); fma2(acc[0][1], d, w0.y); fma2(acc[0][2], d, w1.x); fma2(acc[0][3], d, w1.y);
            d = dup2(av0.y); fma2(acc[1][0], d, w0.x); fma2(acc[1][1], d, w0.y); fma2(acc[1][2], d, w1.x); fma2(acc[1][3], d, w1.y);
            d = dup2(av0.z); fma2(acc[2][0], d, w0.x); fma2(acc[2][1], d, w0.y); fma2(acc[2][2], d, w1.x); fma2(acc[2][3], d, w1.y);
            d = dup2(av0.w); fma2(acc[3][0], d, w0.x); fma2(acc[3][1], d, w0.y); fma2(acc[3][2], d, w1.x); fma2(acc[3][3], d, w1.y);
            d = dup2(av1.x); fma2(acc[4][0], d, w0.x); fma2(acc[4][1], d, w0.y); fma2(acc[4][2], d, w1.x); fma2(acc[4][3], d, w1.y);
            d = dup2(av1.y); fma2(acc[5][0], d, w0.x); fma2(acc[5][1], d, w0.y); fma2(acc[5][2], d, w1.x); fma2(acc[5][3], d, w1.y);
            d = dup2(av1.z); fma2(acc[6][0], d, w0.x); fma2(acc[6][1], d, w0.y); fma2(acc[6][2], d, w1.x); fma2(acc[6][3], d, w1.y);
            d = dup2(av1.w); fma2(acc[7][0], d, w0.x); fma2(acc[7][1], d, w0.y); fma2(acc[7][2], d, w1.x); fma2(acc[7][3], d, w1.y);
        }
        __syncthreads();
    }

    float* outP = ((z == 0) ? g_muP : g_v1P) + ((size_t)ms * Bn + b) * (Pn * Kn);
    int k0 = kg * 8;
#pragma unroll
    for (int i = 0; i < 8; i++) {
        int p = pg * 8 + i;
        if (p >= Pn) continue;
        float4 v0, v1;
        unpack2(acc[i][0], v0.x, v0.y);
        unpack2(acc[i][1], v0.z, v0.w);
        unpack2(acc[i][2], v1.x, v1.y);
        unpack2(acc[i][3], v1.z, v1.w);
        *(float4*)(outP + (size_t)p * Kn + k0)     = v0;
        *(float4*)(outP + (size_t)p * Kn + k0 + 4) = v1;
    }
}

// ---------------------------------------------------------------------------
// Kernel 4: sum the 5 partials for mu_out and v1.
// ---------------------------------------------------------------------------
__global__ __launch_bounds__(256) void k_fix(float* __restrict__ mu_out, int write_mu) {
    int idx = blockIdx.x * 256 + threadIdx.x;
    if (idx >= Bn * Pn * Kn) return;
    const int STR = Bn * Pn * Kn;
    float sm = 0.f, sv = 0.f;
#pragma unroll
    for (int ms = 0; ms < MS; ms++) {
        sm += g_muP[ms * STR + idx];
        sv += g_v1P[ms * STR + idx];
    }
    if (write_mu) mu_out[idx] = sm;
    g_v1[idx] = sv;
}

// ---------------------------------------------------------------------------
// Kernel 5: Sigma_out [32,100,100,64]. One thread per (b,p,q): 64 k's.
// ---------------------------------------------------------------------------
__global__ __launch_bounds__(128) void k_sigma(float* __restrict__ sigma_out) {
    __shared__ float sp_s[Kn];
    int t = threadIdx.x;
    if (t < 16) ((float4*)sp_s)[t] = ((const float4*)g_sp)[t];
    __syncthreads();

    int bpq = blockIdx.x * 128 + t;
    if (bpq >= Bn * Pn * Pn) return;
    int q  = bpq % Pn;
    int bp = bpq / Pn;
    int p  = bp % Pn;

    const int GSTR = Bn * Pn * Pn;
    float g = 0.f;
#pragma unroll
    for (int ms = 0; ms < MS; ms++) g += g_Gp[ms * GSTR + bpq];

    bool diag = (p == q);
    const float* vrow = g_v1 + (size_t)bp * Kn;
    float* orow = sigma_out + (size_t)bpq * Kn;

#pragma unroll 4
    for (int j = 0; j < 16; j++) {
        float4 s = *(const float4*)&sp_s[j * 4];
        float4 v;
        v.x = s.x * g; v.y = s.y * g; v.z = s.z * g; v.w = s.w * g;
        if (diag) {
            float4 d = *(const float4*)(vrow + j * 4);
            v.x += d.x; v.y += d.y; v.z += d.z; v.w += d.w;
        }
        v.x = isfinite(v.x) ? v.x : 0.f;
        v.y = isfinite(v.y) ? v.y : 0.f;
        v.z = isfinite(v.z) ? v.z : 0.f;
        v.w = isfinite(v.w) ? v.w : 0.f;
        int dq = q - j * 4;
        if (dq == 0)      v.x = fabsf(v.x);
        else if (dq == 1) v.y = fabsf(v.y);
        else if (dq == 2) v.z = fabsf(v.z);
        else if (dq == 3) v.w = fabsf(v.w);
        *(float4*)(orow + j * 4) = v;
    }
}

// ---------------------------------------------------------------------------
extern "C" void kernel_launch(void* const* d_in, const int* in_sizes, int n_in,
                              void* d_out, int out_size) {
    const float* mu_in    = (const float*)d_in[0];
    const float* Sigma_in = (const float*)d_in[1];
    const float* w_mu     = (const float*)d_in[2];
    const float* w_sigma  = (const float*)d_in[3];
    float* out = (float*)d_out;

    const long long sigma_elems = (long long)Bn * Pn * Pn * Kn;
    long long sigma_off = (long long)out_size - sigma_elems;
    if (sigma_off < 0) sigma_off = 0;
    int write_mu = (sigma_off >= (long long)Bn * Pn * Kn) ? 1 : 0;
    float* mu_out    = out;
    float* sigma_out = out + sigma_off;

    k_gather<<<(Bn * Pn * Mn + 255) / 256, 256>>>(mu_in, Sigma_in, w_mu, w_sigma);
    k_gram<<<dim3(Bn, 3, MS), 128>>>();
    k_muv1<<<dim3(Bn, 2, MS), 128>>>(w_mu);
    k_fix<<<(Bn * Pn * Kn + 255) / 256, 256>>>(mu_out, write_mu);
    k_sigma<<<(Bn * Pn * Pn + 127) / 128, 128>>>(sigma_out);
}